// round 1
// baseline (speedup 1.0000x reference)
#include <cuda_runtime.h>
#include <math.h>

// Problem constants
#define NN 4096
#define DD 1024
#define HH 2048

// ---------------- scratch (device globals; no allocations allowed) ----------
__device__ float g_V[(size_t)NN * DD];          // 16 MB
__device__ float g_colsum[DD];                  // 4 KB
__device__ float g_feat[(size_t)NN * 2 * DD];   // 32 MB
__device__ float g_hidden[(size_t)NN * HH];     // 32 MB
__device__ float g_scores[(size_t)NN * NN];     // 64 MB

// ---------------- positional encoding ---------------------------------------
__device__ __forceinline__ float pe_val(int pos, int j) {
    // pe[pos][2k]   = sin(pos / 10000^(2k/D))
    // pe[pos][2k+1] = cos(pos / 10000^(2k/D))
    float even  = (float)(j & ~1);
    float denom = powf(10000.0f, even * (1.0f / (float)DD));
    float arg   = (float)pos / denom;
    return (j & 1) ? cosf(arg) : sinf(arg);
}

// ---------------- small kernels ----------------------------------------------
__global__ void zero_kernel(float* p, int n) {
    int i = blockIdx.x * blockDim.x + threadIdx.x;
    if (i < n) p[i] = 0.0f;
}

// partial column sums of E = PE * X, 128 rows per block, atomicAdd merge
#define CS_ROWS 128
__global__ void colsum_kernel(const float* __restrict__ X, float* __restrict__ colsum) {
    int j  = blockIdx.x * blockDim.x + threadIdx.x;   // column
    int r0 = blockIdx.y * CS_ROWS;
    float s = 0.0f;
    #pragma unroll 4
    for (int i = 0; i < CS_ROWS; i++) {
        int pos = r0 + i;
        s += pe_val(pos, j) * X[(size_t)pos * DD + j];
    }
    atomicAdd(&colsum[j], s);
}

// feat = [X, (colsum - PE*X)/(N-1)]  (N, 2D)
__global__ void feat_kernel(const float* __restrict__ X,
                            const float* __restrict__ colsum,
                            float* __restrict__ feat) {
    int idx = blockIdx.x * blockDim.x + threadIdx.x;   // over N*2D
    int row = idx >> 11;          // / 2048
    int col = idx & 2047;         // % 2048
    float v;
    if (col < DD) {
        v = X[(size_t)row * DD + col];
    } else {
        int j = col - DD;
        float e = pe_val(row, j) * X[(size_t)row * DD + j];
        v = (colsum[j] - e) * (1.0f / (float)(NN - 1));
    }
    feat[idx] = v;
}

// row softmax, one block per row
__global__ void softmax_kernel(float* __restrict__ S, int n) {
    __shared__ float smax[8];
    __shared__ float ssum[8];
    float* row = S + (size_t)blockIdx.x * n;
    int tid = threadIdx.x;         // 256 threads
    int lane = tid & 31, warp = tid >> 5;

    float m = -1e30f;
    for (int j = tid; j < n; j += 256) m = fmaxf(m, row[j]);
    #pragma unroll
    for (int o = 16; o > 0; o >>= 1) m = fmaxf(m, __shfl_xor_sync(0xffffffffu, m, o));
    if (lane == 0) smax[warp] = m;
    __syncthreads();
    if (tid < 8) {
        float v = smax[tid];
        #pragma unroll
        for (int o = 4; o > 0; o >>= 1) v = fmaxf(v, __shfl_xor_sync(0xffu, v, o));
        if (tid == 0) smax[0] = v;
    }
    __syncthreads();
    m = smax[0];

    float s = 0.0f;
    for (int j = tid; j < n; j += 256) {
        float e = __expf(row[j] - m);
        row[j] = e;
        s += e;
    }
    #pragma unroll
    for (int o = 16; o > 0; o >>= 1) s += __shfl_xor_sync(0xffffffffu, s, o);
    if (lane == 0) ssum[warp] = s;
    __syncthreads();
    if (tid < 8) {
        float v = ssum[tid];
        #pragma unroll
        for (int o = 4; o > 0; o >>= 1) v += __shfl_xor_sync(0xffu, v, o);
        if (tid == 0) ssum[0] = v;
    }
    __syncthreads();
    float inv = 1.0f / ssum[0];
    for (int j = tid; j < n; j += 256) row[j] *= inv;
}

// ---------------- SGEMM: C(M,N) = A(M,K) @ B(K,N) [+bias] [relu] -------------
#define BM 128
#define BN 128
#define BK 16
#define TM 8
#define TN 8

template<bool BIAS, bool RELU>
__global__ __launch_bounds__(256, 2)
void sgemm_kernel(const float* __restrict__ A, const float* __restrict__ B,
                  const float* __restrict__ bias, float* __restrict__ C,
                  int M, int N, int K) {
    __shared__ float As[BK][BM];
    __shared__ float Bs[BK][BN];

    const int tid = threadIdx.x;            // 256
    const int tx  = tid & 15;               // 0..15 -> col group
    const int ty  = tid >> 4;               // 0..15 -> row group
    const int cx  = blockIdx.x * BN;
    const int cy  = blockIdx.y * BM;

    // A loads: 128x16 tile, float4. tid/4 -> row (0..63, x2), (tid&3)*4 -> col
    const int aRow = tid >> 2;
    const int aCol = (tid & 3) << 2;
    // B loads: 16x128 tile, float4. tid/32 -> row (0..7, x2), (tid&31)*4 -> col
    const int bRow = tid >> 5;
    const int bCol = (tid & 31) << 2;

    const float* Ab = A + (size_t)cy * K;
    const float* Bb = B + cx;

    float acc[TM][TN];
    #pragma unroll
    for (int i = 0; i < TM; i++)
        #pragma unroll
        for (int j = 0; j < TN; j++) acc[i][j] = 0.0f;

    for (int kt = 0; kt < K; kt += BK) {
        #pragma unroll
        for (int i = 0; i < 2; i++) {
            int r = aRow + i * 64;
            float4 v = *(const float4*)(Ab + (size_t)r * K + kt + aCol);
            As[aCol + 0][r] = v.x;
            As[aCol + 1][r] = v.y;
            As[aCol + 2][r] = v.z;
            As[aCol + 3][r] = v.w;
        }
        #pragma unroll
        for (int i = 0; i < 2; i++) {
            int r = bRow + i * 8;
            *(float4*)(&Bs[r][bCol]) = *(const float4*)(Bb + (size_t)(kt + r) * N + bCol);
        }
        __syncthreads();

        #pragma unroll
        for (int k = 0; k < BK; k++) {
            float ra[TM], rb[TN];
            #pragma unroll
            for (int i = 0; i < TM; i += 4) {
                float4 v = *(const float4*)(&As[k][ty * TM + i]);
                ra[i] = v.x; ra[i+1] = v.y; ra[i+2] = v.z; ra[i+3] = v.w;
            }
            #pragma unroll
            for (int j = 0; j < TN; j += 4) {
                float4 v = *(const float4*)(&Bs[k][tx * TN + j]);
                rb[j] = v.x; rb[j+1] = v.y; rb[j+2] = v.z; rb[j+3] = v.w;
            }
            #pragma unroll
            for (int i = 0; i < TM; i++)
                #pragma unroll
                for (int j = 0; j < TN; j++)
                    acc[i][j] += ra[i] * rb[j];
        }
        __syncthreads();
    }

    #pragma unroll
    for (int i = 0; i < TM; i++) {
        int row = cy + ty * TM + i;
        #pragma unroll
        for (int j = 0; j < TN; j += 4) {
            int col = cx + tx * TN + j;
            float4 v;
            v.x = acc[i][j + 0];
            v.y = acc[i][j + 1];
            v.z = acc[i][j + 2];
            v.w = acc[i][j + 3];
            if (BIAS) {
                v.x += bias[col + 0];
                v.y += bias[col + 1];
                v.z += bias[col + 2];
                v.w += bias[col + 3];
            }
            if (RELU) {
                v.x = fmaxf(v.x, 0.0f);
                v.y = fmaxf(v.y, 0.0f);
                v.z = fmaxf(v.z, 0.0f);
                v.w = fmaxf(v.w, 0.0f);
            }
            *(float4*)(&C[(size_t)row * N + col]) = v;
        }
    }
}

// ---------------- driver ------------------------------------------------------
extern "C" void kernel_launch(void* const* d_in, const int* in_sizes, int n_in,
                              void* d_out, int out_size) {
    const float* X  = (const float*)d_in[0];
    // d_in[1] = mask (int32), unused by the module
    const float* Wv = (const float*)d_in[2];
    const float* bv = (const float*)d_in[3];
    const float* W1 = (const float*)d_in[4];
    const float* b1 = (const float*)d_in[5];
    const float* W2 = (const float*)d_in[6];
    const float* b2 = (const float*)d_in[7];
    float* out = (float*)d_out;

    void* p;
    cudaGetSymbolAddress(&p, g_V);      float* V      = (float*)p;
    cudaGetSymbolAddress(&p, g_colsum); float* colsum = (float*)p;
    cudaGetSymbolAddress(&p, g_feat);   float* feat   = (float*)p;
    cudaGetSymbolAddress(&p, g_hidden); float* hidden = (float*)p;
    cudaGetSymbolAddress(&p, g_scores); float* scores = (float*)p;

    // leave-one-out feature path
    zero_kernel<<<4, 256>>>(colsum, DD);
    colsum_kernel<<<dim3(DD / 256, NN / CS_ROWS), 256>>>(X, colsum);
    feat_kernel<<<(NN * 2 * DD) / 256, 256>>>(X, colsum, feat);

    // V = X @ Wv + bv
    sgemm_kernel<true, false><<<dim3(DD / BN, NN / BM), 256>>>(X, Wv, bv, V, NN, DD, DD);

    // hidden = relu(feat @ W1 + b1)
    sgemm_kernel<true, true><<<dim3(HH / BN, NN / BM), 256>>>(feat, W1, b1, hidden, NN, HH, 2 * DD);

    // scores = hidden @ W2 + b2
    sgemm_kernel<true, false><<<dim3(NN / BN, NN / BM), 256>>>(hidden, W2, b2, scores, NN, NN, HH);

    // softmax rows
    softmax_kernel<<<NN, 256>>>(scores, NN);

    // out = att @ V
    sgemm_kernel<false, false><<<dim3(DD / BN, NN / BM), 256>>>(scores, V, nullptr, out, NN, DD, NN);
}

// round 3
// speedup vs baseline: 2.2458x; 2.2458x over previous
#include <cuda_runtime.h>
#include <cuda_bf16.h>
#include <math.h>
#include <stdint.h>

// Problem constants
#define NN 4096
#define DD 1024
#define HH 2048

typedef __nv_bfloat16 bf16;

// ---------------- scratch (device globals; no allocations allowed) ----------
__device__ float g_colsum[DD];
__device__ float g_V[(size_t)NN * DD];                 // 16 MB
__device__ float g_scores[(size_t)NN * NN];            // 64 MB

__device__ bf16 g_Xhi[(size_t)NN * DD],      g_Xlo[(size_t)NN * DD];
__device__ bf16 g_WvThi[(size_t)DD * DD],    g_WvTlo[(size_t)DD * DD];
__device__ bf16 g_feathi[(size_t)NN * 2*DD], g_featlo[(size_t)NN * 2*DD];
__device__ bf16 g_W1Thi[(size_t)HH * 2*DD],  g_W1Tlo[(size_t)HH * 2*DD];
__device__ bf16 g_hidhi[(size_t)NN * HH],    g_hidlo[(size_t)NN * HH];
__device__ bf16 g_W2Thi[(size_t)NN * HH],    g_W2Tlo[(size_t)NN * HH];
__device__ bf16 g_atthi[(size_t)NN * NN],    g_attlo[(size_t)NN * NN];
__device__ bf16 g_VThi[(size_t)DD * NN],     g_VTlo[(size_t)DD * NN];

// ---------------- helpers -----------------------------------------------------
__device__ __forceinline__ uint32_t smem_u32(const void* p) {
    uint32_t a;
    asm("{ .reg .u64 t; cvta.to.shared.u64 t, %1; cvt.u32.u64 %0, t; }" : "=r"(a) : "l"(p));
    return a;
}
__device__ __forceinline__ void cp_async16(uint32_t saddr, const void* gaddr) {
    asm volatile("cp.async.cg.shared.global [%0], [%1], 16;" :: "r"(saddr), "l"(gaddr));
}
__device__ __forceinline__ void cp_commit() {
    asm volatile("cp.async.commit_group;");
}
template<int N>
__device__ __forceinline__ void cp_wait() {
    asm volatile("cp.async.wait_group %0;" :: "n"(N));
}
__device__ __forceinline__ void ldsm_x4(uint32_t addr, uint32_t& r0, uint32_t& r1,
                                        uint32_t& r2, uint32_t& r3) {
    asm volatile("ldmatrix.sync.aligned.m8n8.x4.shared.b16 {%0,%1,%2,%3}, [%4];"
                 : "=r"(r0), "=r"(r1), "=r"(r2), "=r"(r3) : "r"(addr));
}
__device__ __forceinline__ void mma_bf16(float* c, const uint32_t* a, const uint32_t* b) {
    asm volatile(
        "mma.sync.aligned.m16n8k16.row.col.f32.bf16.bf16.f32 "
        "{%0,%1,%2,%3}, {%4,%5,%6,%7}, {%8,%9}, {%0,%1,%2,%3};"
        : "+f"(c[0]), "+f"(c[1]), "+f"(c[2]), "+f"(c[3])
        : "r"(a[0]), "r"(a[1]), "r"(a[2]), "r"(a[3]), "r"(b[0]), "r"(b[1]));
}

// ---------------- GEMM: C(M,N) = A @ B'^T via bf16x3 mma.sync -----------------
// A: [M][K] row-major bf16 (hi/lo). B': [N][K] row-major bf16 (hi/lo).
// 3 internal passes: Ahi*Bhi + Ahi*Blo + Alo*Bhi.
#define BM 128
#define BN 128
#define BK 32
#define STAGES 4
#define ROWB 80                      // padded row stride in bytes (32 bf16 + 8 pad)
#define ATILE (BM * ROWB)            // 10240 B
#define STAGE_BYTES (2 * ATILE)      // A + B per stage = 20480 B
#define GSMEM (STAGES * STAGE_BYTES) // 81920 B

__device__ __forceinline__ void load_chunk(uint32_t sstage,
                                           const bf16* __restrict__ Ap,
                                           const bf16* __restrict__ Bp,
                                           int K, int kt, int cy, int cx, int tid) {
    #pragma unroll
    for (int i = 0; i < 2; i++) {
        int u = tid + i * 256;               // 0..511
        int r = u >> 2, q = u & 3;           // row, 16B-unit within 64B of data
        cp_async16(sstage + r * ROWB + q * 16,
                   Ap + (size_t)(cy + r) * K + kt + q * 8);
    }
    #pragma unroll
    for (int i = 0; i < 2; i++) {
        int u = tid + i * 256;
        int r = u >> 2, q = u & 3;
        cp_async16(sstage + ATILE + r * ROWB + q * 16,
                   Bp + (size_t)(cx + r) * K + kt + q * 8);
    }
}

template<bool BIAS, bool RELU, bool SPLIT>
__global__ __launch_bounds__(256)
void gemm_mma(const bf16* __restrict__ Ahi, const bf16* __restrict__ Alo,
              const bf16* __restrict__ Bhi, const bf16* __restrict__ Blo,
              const float* __restrict__ bias,
              float* __restrict__ Cf, bf16* __restrict__ Chi, bf16* __restrict__ Clo,
              int M, int Nn, int K) {
    extern __shared__ char smem[];
    const uint32_t sb = smem_u32(smem);
    const int tid  = threadIdx.x;
    const int lane = tid & 31;
    const int wid  = tid >> 5;
    const int wm   = wid >> 2;          // 0..1  (M)
    const int wn   = wid & 3;           // 0..3  (N)
    const int cx   = blockIdx.x * BN;
    const int cy   = blockIdx.y * BM;

    const int NCK = K >> 5;
    const int NC3 = NCK * 3;

    float acc[4][4][4];
    #pragma unroll
    for (int i = 0; i < 4; i++)
        #pragma unroll
        for (int j = 0; j < 4; j++)
            #pragma unroll
            for (int k = 0; k < 4; k++) acc[i][j][k] = 0.0f;

    // per-lane ldmatrix address components
    const uint32_t aoff = (uint32_t)((wm * 64 + (lane & 15)) * ROWB + ((lane & 16) ? 16 : 0));
    const uint32_t boff = (uint32_t)((wn * 32 + (lane & 7) + ((lane & 16) ? 8 : 0)) * ROWB
                                     + ((lane & 8) ? 16 : 0));

    // prefetch
    #pragma unroll
    for (int c = 0; c < STAGES - 1; c++) {
        int pass = c / NCK;
        const bf16* Ap = (pass == 2) ? Alo : Ahi;
        const bf16* Bp = (pass == 1) ? Blo : Bhi;
        load_chunk(sb + (c % STAGES) * STAGE_BYTES, Ap, Bp, K, (c % NCK) * BK, cy, cx, tid);
        cp_commit();
    }
    cp_wait<STAGES - 2>();
    __syncthreads();

    for (int c = 0; c < NC3; c++) {
        const uint32_t st = sb + (c % STAGES) * STAGE_BYTES;
        #pragma unroll
        for (int ks = 0; ks < 2; ks++) {
            uint32_t a[4][4], b[4][2];
            #pragma unroll
            for (int mf = 0; mf < 4; mf++)
                ldsm_x4(st + aoff + mf * (16 * ROWB) + ks * 32,
                        a[mf][0], a[mf][1], a[mf][2], a[mf][3]);
            #pragma unroll
            for (int nf2 = 0; nf2 < 2; nf2++) {
                uint32_t r0, r1, r2, r3;
                ldsm_x4(st + ATILE + boff + nf2 * (16 * ROWB) + ks * 32, r0, r1, r2, r3);
                b[nf2 * 2 + 0][0] = r0; b[nf2 * 2 + 0][1] = r1;
                b[nf2 * 2 + 1][0] = r2; b[nf2 * 2 + 1][1] = r3;
            }
            #pragma unroll
            for (int mf = 0; mf < 4; mf++)
                #pragma unroll
                for (int nf = 0; nf < 4; nf++)
                    mma_bf16(acc[mf][nf], a[mf], b[nf]);
        }
        int nc = c + STAGES - 1;
        if (nc < NC3) {
            int pass = nc / NCK;
            const bf16* Ap = (pass == 2) ? Alo : Ahi;
            const bf16* Bp = (pass == 1) ? Blo : Bhi;
            load_chunk(sb + (nc % STAGES) * STAGE_BYTES, Ap, Bp, K, (nc % NCK) * BK, cy, cx, tid);
        }
        cp_commit();
        cp_wait<STAGES - 2>();
        __syncthreads();
    }

    // ---------------- epilogue -----------------------------------------------
    const int gid = lane >> 2;
    const int tig = lane & 3;
    #pragma unroll
    for (int mf = 0; mf < 4; mf++) {
        #pragma unroll
        for (int nf = 0; nf < 4; nf++) {
            const int row0 = cy + wm * 64 + mf * 16 + gid;
            const int col  = cx + wn * 32 + nf * 8 + tig * 2;
            float v0 = acc[mf][nf][0], v1 = acc[mf][nf][1];
            float v2 = acc[mf][nf][2], v3 = acc[mf][nf][3];
            if (BIAS) {
                float b0 = bias[col], b1 = bias[col + 1];
                v0 += b0; v1 += b1; v2 += b0; v3 += b1;
            }
            if (RELU) {
                v0 = fmaxf(v0, 0.f); v1 = fmaxf(v1, 0.f);
                v2 = fmaxf(v2, 0.f); v3 = fmaxf(v3, 0.f);
            }
            if (!SPLIT) {
                float2 p0 = make_float2(v0, v1);
                float2 p1 = make_float2(v2, v3);
                *(float2*)(Cf + (size_t)row0 * Nn + col)       = p0;
                *(float2*)(Cf + (size_t)(row0 + 8) * Nn + col) = p1;
            } else {
                bf16 h0 = __float2bfloat16(v0), h1 = __float2bfloat16(v1);
                bf16 h2 = __float2bfloat16(v2), h3 = __float2bfloat16(v3);
                bf16 l0 = __float2bfloat16(v0 - __bfloat162float(h0));
                bf16 l1 = __float2bfloat16(v1 - __bfloat162float(h1));
                bf16 l2 = __float2bfloat16(v2 - __bfloat162float(h2));
                bf16 l3 = __float2bfloat16(v3 - __bfloat162float(h3));
                __nv_bfloat162 hp0; hp0.x = h0; hp0.y = h1;
                __nv_bfloat162 hp1; hp1.x = h2; hp1.y = h3;
                __nv_bfloat162 lp0; lp0.x = l0; lp0.y = l1;
                __nv_bfloat162 lp1; lp1.x = l2; lp1.y = l3;
                *(__nv_bfloat162*)(Chi + (size_t)row0 * Nn + col)       = hp0;
                *(__nv_bfloat162*)(Chi + (size_t)(row0 + 8) * Nn + col) = hp1;
                *(__nv_bfloat162*)(Clo + (size_t)row0 * Nn + col)       = lp0;
                *(__nv_bfloat162*)(Clo + (size_t)(row0 + 8) * Nn + col) = lp1;
            }
        }
    }
}

// ---------------- positional encoding ----------------------------------------
__device__ __forceinline__ float pe_val(int pos, int j) {
    float even  = (float)(j & ~1);
    float denom = powf(10000.0f, even * (1.0f / (float)DD));
    float arg   = (float)pos / denom;
    return (j & 1) ? cosf(arg) : sinf(arg);
}

// ---------------- elementwise kernels -----------------------------------------
__global__ void zero_kernel(float* p, int n) {
    int i = blockIdx.x * blockDim.x + threadIdx.x;
    if (i < n) p[i] = 0.0f;
}

#define CS_ROWS 128
__global__ void colsum_kernel(const float* __restrict__ X, float* __restrict__ colsum) {
    int j  = blockIdx.x * blockDim.x + threadIdx.x;
    int r0 = blockIdx.y * CS_ROWS;
    float s = 0.0f;
    #pragma unroll 4
    for (int i = 0; i < CS_ROWS; i++) {
        int pos = r0 + i;
        s += pe_val(pos, j) * X[(size_t)pos * DD + j];
    }
    atomicAdd(&colsum[j], s);
}

__device__ __forceinline__ void split_store(bf16* hi, bf16* lo, size_t idx, float v) {
    bf16 h = __float2bfloat16(v);
    hi[idx] = h;
    lo[idx] = __float2bfloat16(v - __bfloat162float(h));
}

__global__ void feat_split_kernel(const float* __restrict__ X,
                                  const float* __restrict__ colsum,
                                  bf16* __restrict__ fhi, bf16* __restrict__ flo) {
    int idx = blockIdx.x * blockDim.x + threadIdx.x;
    int row = idx >> 11;
    int col = idx & 2047;
    float v;
    if (col < DD) {
        v = X[(size_t)row * DD + col];
    } else {
        int j = col - DD;
        float e = pe_val(row, j) * X[(size_t)row * DD + j];
        v = (colsum[j] - e) * (1.0f / (float)(NN - 1));
    }
    split_store(fhi, flo, idx, v);
}

__global__ void split_kernel(const float* __restrict__ src,
                             bf16* __restrict__ hi, bf16* __restrict__ lo, int n) {
    int i = blockIdx.x * blockDim.x + threadIdx.x;
    if (i < n) split_store(hi, lo, i, src[i]);
}

// transpose + split: src [R][C] fp32 -> dst [C][R] bf16 hi/lo
__global__ void tsplit_kernel(const float* __restrict__ src,
                              bf16* __restrict__ dhi, bf16* __restrict__ dlo,
                              int R, int C) {
    __shared__ float t[32][33];
    int bx = blockIdx.x * 32;
    int by = blockIdx.y * 32;
    int tx = threadIdx.x, ty = threadIdx.y;
    #pragma unroll
    for (int i = 0; i < 4; i++)
        t[ty + i * 8][tx] = src[(size_t)(by + ty + i * 8) * C + bx + tx];
    __syncthreads();
    #pragma unroll
    for (int i = 0; i < 4; i++) {
        float v = t[tx][ty + i * 8];
        split_store(dhi, dlo, (size_t)(bx + ty + i * 8) * R + by + tx, v);
    }
}

// row softmax over scores; writes att split bf16
__global__ void softmax_split_kernel(float* __restrict__ S,
                                     bf16* __restrict__ ahi, bf16* __restrict__ alo, int n) {
    __shared__ float red[8];
    float* row = S + (size_t)blockIdx.x * n;
    int tid = threadIdx.x;
    int lane = tid & 31, warp = tid >> 5;

    float m = -1e30f;
    for (int j = tid; j < n; j += 256) m = fmaxf(m, row[j]);
    #pragma unroll
    for (int o = 16; o > 0; o >>= 1) m = fmaxf(m, __shfl_xor_sync(0xffffffffu, m, o));
    if (lane == 0) red[warp] = m;
    __syncthreads();
    if (tid < 8) {
        float v = red[tid];
        #pragma unroll
        for (int o = 4; o > 0; o >>= 1) v = fmaxf(v, __shfl_xor_sync(0xffu, v, o));
        if (tid == 0) red[0] = v;
    }
    __syncthreads();
    m = red[0];
    __syncthreads();

    float s = 0.0f;
    for (int j = tid; j < n; j += 256) {
        float e = __expf(row[j] - m);
        row[j] = e;
        s += e;
    }
    #pragma unroll
    for (int o = 16; o > 0; o >>= 1) s += __shfl_xor_sync(0xffffffffu, s, o);
    if (lane == 0) red[warp] = s;
    __syncthreads();
    if (tid < 8) {
        float v = red[tid];
        #pragma unroll
        for (int o = 4; o > 0; o >>= 1) v += __shfl_xor_sync(0xffu, v, o);
        if (tid == 0) red[0] = v;
    }
    __syncthreads();
    float inv = 1.0f / red[0];
    size_t base = (size_t)blockIdx.x * n;
    for (int j = tid; j < n; j += 256) {
        float a = row[j] * inv;
        split_store(ahi, alo, base + j, a);
    }
}

// ---------------- driver ------------------------------------------------------
extern "C" void kernel_launch(void* const* d_in, const int* in_sizes, int n_in,
                              void* d_out, int out_size) {
    const float* X  = (const float*)d_in[0];
    const float* Wv = (const float*)d_in[2];
    const float* bv = (const float*)d_in[3];
    const float* W1 = (const float*)d_in[4];
    const float* b1 = (const float*)d_in[5];
    const float* W2 = (const float*)d_in[6];
    const float* b2 = (const float*)d_in[7];
    float* out = (float*)d_out;

    void* p;
    cudaGetSymbolAddress(&p, g_colsum); float* colsum = (float*)p;
    cudaGetSymbolAddress(&p, g_V);      float* V      = (float*)p;
    cudaGetSymbolAddress(&p, g_scores); float* scores = (float*)p;
    cudaGetSymbolAddress(&p, g_Xhi);    bf16* Xhi   = (bf16*)p;
    cudaGetSymbolAddress(&p, g_Xlo);    bf16* Xlo   = (bf16*)p;
    cudaGetSymbolAddress(&p, g_WvThi);  bf16* WvThi = (bf16*)p;
    cudaGetSymbolAddress(&p, g_WvTlo);  bf16* WvTlo = (bf16*)p;
    cudaGetSymbolAddress(&p, g_feathi); bf16* fthi  = (bf16*)p;
    cudaGetSymbolAddress(&p, g_featlo); bf16* ftlo  = (bf16*)p;
    cudaGetSymbolAddress(&p, g_W1Thi);  bf16* W1Thi = (bf16*)p;
    cudaGetSymbolAddress(&p, g_W1Tlo);  bf16* W1Tlo = (bf16*)p;
    cudaGetSymbolAddress(&p, g_hidhi);  bf16* hdhi  = (bf16*)p;
    cudaGetSymbolAddress(&p, g_hidlo);  bf16* hdlo  = (bf16*)p;
    cudaGetSymbolAddress(&p, g_W2Thi);  bf16* W2Thi = (bf16*)p;
    cudaGetSymbolAddress(&p, g_W2Tlo);  bf16* W2Tlo = (bf16*)p;
    cudaGetSymbolAddress(&p, g_atthi);  bf16* athi  = (bf16*)p;
    cudaGetSymbolAddress(&p, g_attlo);  bf16* atlo  = (bf16*)p;
    cudaGetSymbolAddress(&p, g_VThi);   bf16* VThi  = (bf16*)p;
    cudaGetSymbolAddress(&p, g_VTlo);   bf16* VTlo  = (bf16*)p;

    cudaFuncSetAttribute(gemm_mma<true,  false, false>,
                         cudaFuncAttributeMaxDynamicSharedMemorySize, GSMEM);
    cudaFuncSetAttribute(gemm_mma<true,  true,  true>,
                         cudaFuncAttributeMaxDynamicSharedMemorySize, GSMEM);
    cudaFuncSetAttribute(gemm_mma<false, false, false>,
                         cudaFuncAttributeMaxDynamicSharedMemorySize, GSMEM);

    // --- operand prep --------------------------------------------------------
    zero_kernel<<<4, 256>>>(colsum, DD);
    colsum_kernel<<<dim3(DD / 256, NN / CS_ROWS), 256>>>(X, colsum);
    feat_split_kernel<<<(NN * 2 * DD) / 256, 256>>>(X, colsum, fthi, ftlo);
    split_kernel<<<(NN * DD) / 256, 256>>>(X, Xhi, Xlo, NN * DD);
    tsplit_kernel<<<dim3(DD / 32, DD / 32),     dim3(32, 8)>>>(Wv, WvThi, WvTlo, DD, DD);
    tsplit_kernel<<<dim3(HH / 32, (2*DD) / 32), dim3(32, 8)>>>(W1, W1Thi, W1Tlo, 2 * DD, HH);
    tsplit_kernel<<<dim3(NN / 32, HH / 32),     dim3(32, 8)>>>(W2, W2Thi, W2Tlo, HH, NN);

    // --- GEMM1: V = X @ Wv + bv  (M=4096, N=1024, K=1024) --------------------
    gemm_mma<true, false, false><<<dim3(DD / BN, NN / BM), 256, GSMEM>>>(
        Xhi, Xlo, WvThi, WvTlo, bv, V, nullptr, nullptr, NN, DD, DD);
    tsplit_kernel<<<dim3(DD / 32, NN / 32), dim3(32, 8)>>>(V, VThi, VTlo, NN, DD);

    // --- GEMM2: hidden = relu(feat @ W1 + b1) (4096,2048,2048) ---------------
    gemm_mma<true, true, true><<<dim3(HH / BN, NN / BM), 256, GSMEM>>>(
        fthi, ftlo, W1Thi, W1Tlo, b1, nullptr, hdhi, hdlo, NN, HH, 2 * DD);

    // --- GEMM3: scores = hidden @ W2 + b2 (4096,4096,2048) -------------------
    gemm_mma<true, false, false><<<dim3(NN / BN, NN / BM), 256, GSMEM>>>(
        hdhi, hdlo, W2Thi, W2Tlo, b2, scores, nullptr, nullptr, NN, NN, HH);

    // --- softmax -> att split -------------------------------------------------
    softmax_split_kernel<<<NN, 256>>>(scores, athi, atlo, NN);

    // --- GEMM4: out = att @ V (4096,1024,4096) --------------------------------
    gemm_mma<false, false, false><<<dim3(DD / BN, NN / BM), 256, GSMEM>>>(
        athi, atlo, VThi, VTlo, nullptr, out, nullptr, nullptr, NN, DD, NN);
}